// round 16
// baseline (speedup 1.0000x reference)
#include <cuda_runtime.h>
#include <cstdint>

#define N_NODES 8192
#define N_EDGES 24576
#define D_FEAT  64
#define N_QUBITS 16
#define PI_F 3.14159265358979f

#define SCAN_BLOCKS (148 * 16)           // 2368: 2 waves -> natural load balance
#define SCAN_THREADS 256
#define NODE_BLOCKS (N_NODES / 8)        // blocks 0..1023 run node prologue

#define EDGE_BLOCKS (N_EDGES * 4 / 256)  // 384 (4 lanes per edge)

// Scratch (no device mallocs allowed)
__device__ int      g_idx_o[N_EDGES];
__device__ int      g_idx_i[N_EDGES];
__device__ float    g_H[N_NODES * 32];   // [n][0:16]=X[n]@W_top, [n][16:32]=X[n]@W_bot
__device__ unsigned g_min_bits;
__device__ unsigned g_max_bits;
__device__ unsigned g_arrive;

// ---------------------------------------------------------------------------
// Fused: (a) node precompute prologue on blocks < NODE_BLOCKS,
//        (b) streaming scan of both one-hot incidence matrices.
// Streaming loads use __ldcs (evict-first) — data is single-use. All hot-loop
// indexing is 32-bit (total4 < 2^31). Nonzero (==1.0f) at linear pos p of
// [N_NODES, N_EDGES] row-major means idx[p % E] = p / E.
// ---------------------------------------------------------------------------
__global__ void __launch_bounds__(SCAN_THREADS)
scan_kernel(const uint4* __restrict__ Mo,
            const uint4* __restrict__ Mi,
            const float* __restrict__ X,
            const float* __restrict__ W) {
    const int tid = threadIdx.x;

    if (blockIdx.x == 0 && tid == 0) {
        g_min_bits = 0x7F800000u;   // +inf
        g_max_bits = 0x00000000u;   // relu outputs >= 0
        g_arrive   = 0u;
    }

    // ---- node prologue: Hs[n][q], Ht[n][q] for 8 nodes per block ----
    if (blockIdx.x < NODE_BLOCKS) {
        __shared__ float sW[2 * D_FEAT * N_QUBITS];   // 8 KB
        __shared__ float sX[8][D_FEAT];

        const int wid  = tid >> 5;
        const int lane = tid & 31;

        const float4* W4 = (const float4*)W;
        ((float4*)sW)[tid]       = W4[tid];
        ((float4*)sW)[tid + 256] = W4[tid + 256];

        const int n = blockIdx.x * 8 + wid;
        ((float2*)sX[wid])[lane] = ((const float2*)(X + (long)n * D_FEAT))[lane];
        __syncthreads();

        const int q    = lane & 15;
        const int half = lane >> 4;   // 0 = W[0:64], 1 = W[64:128]
        const float* w = sW + half * D_FEAT * N_QUBITS + q;
        const float* x = sX[wid];

        float acc = 0.0f;
#pragma unroll
        for (int d = 0; d < D_FEAT; d++)
            acc = fmaf(x[d], w[d * N_QUBITS], acc);

        g_H[(long)n * 32 + lane] = acc;   // coalesced 128B per warp
    }

    // ---- streaming scan (32-bit indices; evict-first loads) ----
    const unsigned total4 = (unsigned)(N_NODES / 4) * N_EDGES;  // 50,331,648
    const unsigned stride = SCAN_BLOCKS * SCAN_THREADS;
    unsigned i = blockIdx.x * SCAN_THREADS + tid;

#define PROCESS(v, I, IDX)                                              \
    if (((v).x | (v).y | (v).z | (v).w) != 0u) {                        \
        unsigned base = (I) * 4u;                                       \
        unsigned n = base / N_EDGES;                                    \
        unsigned e = base % N_EDGES;                                    \
        if ((v).x != 0u) IDX[e + 0] = n;                                \
        if ((v).y != 0u) IDX[e + 1] = n;                                \
        if ((v).z != 0u) IDX[e + 2] = n;                                \
        if ((v).w != 0u) IDX[e + 3] = n;                                \
    }

    for (; i + stride < total4; i += 2 * stride) {
        uint4 a0 = __ldcs(&Mo[i]);
        uint4 a1 = __ldcs(&Mo[i + stride]);
        uint4 b0 = __ldcs(&Mi[i]);
        uint4 b1 = __ldcs(&Mi[i + stride]);
        PROCESS(a0, i,          g_idx_o)
        PROCESS(a1, i + stride, g_idx_o)
        PROCESS(b0, i,          g_idx_i)
        PROCESS(b1, i + stride, g_idx_i)
    }
    for (; i < total4; i += stride) {
        uint4 a = __ldcs(&Mo[i]);
        uint4 b = __ldcs(&Mi[i]);
        PROCESS(a, i, g_idx_o)
        PROCESS(b, i, g_idx_i)
    }
#undef PROCESS
    // implicit programmatic-launch completion at kernel end: all stores above
    // are visible to the PDL-gated consumer after cudaGridDependencySynchronize.
}

// ---------------------------------------------------------------------------
// Edge stage, 4 lanes per edge: lane j of edge e computes qubits [4j, 4j+4)
//   h = relu(Hs[src[e]][4j..] + Ht[tgt[e]][4j..] + b[4j..])
// Launched with PDL: blocks start while scan_kernel drains; scan-independent
// setup (bias load, index math) runs before cudaGridDependencySynchronize().
// Global min/max via atomics + single-wave grid barrier (384 blocks <= 444
// resident slots), normalize in-register, coalesced store.
// ---------------------------------------------------------------------------
__global__ void __launch_bounds__(256, 3)
edge_kernel(const float* __restrict__ b,
            float* __restrict__ out) {
    __shared__ float s_min[8], s_max[8];
    __shared__ float s_lo, s_hi;

    const int tid = threadIdx.x;
    const int j   = tid & 3;
    const int e   = blockIdx.x * 64 + (tid >> 2);

    // scan-independent work first (overlaps with scan tail under PDL)
    const float4 bb = ((const float4*)b)[j];

    // wait for scan_kernel's writes (g_idx_*, g_H, min/max reset) to be visible
    cudaGridDependencySynchronize();

    const int src = g_idx_o[e];
    const int tgt = g_idx_i[e];

    const float4 a = ((const float4*)(g_H + (long)src * 32))[j];
    const float4 c = ((const float4*)(g_H + (long)tgt * 32 + 16))[j];

    float4 h;
    h.x = fmaxf(a.x + c.x + bb.x, 0.0f);
    h.y = fmaxf(a.y + c.y + bb.y, 0.0f);
    h.z = fmaxf(a.z + c.z + bb.z, 0.0f);
    h.w = fmaxf(a.w + c.w + bb.w, 0.0f);

    float tmin = fminf(fminf(h.x, h.y), fminf(h.z, h.w));
    float tmax = fmaxf(fmaxf(h.x, h.y), fmaxf(h.z, h.w));
#pragma unroll
    for (int off = 16; off > 0; off >>= 1) {
        tmin = fminf(tmin, __shfl_xor_sync(0xFFFFFFFF, tmin, off));
        tmax = fmaxf(tmax, __shfl_xor_sync(0xFFFFFFFF, tmax, off));
    }
    const int wid = tid >> 5, lid = tid & 31;
    if (lid == 0) { s_min[wid] = tmin; s_max[wid] = tmax; }
    __syncthreads();

    if (tid == 0) {
        float bmin = s_min[0], bmax = s_max[0];
#pragma unroll
        for (int w = 1; w < 8; w++) {
            bmin = fminf(bmin, s_min[w]);
            bmax = fmaxf(bmax, s_max[w]);
        }
        // nonneg floats: uint bit pattern preserves ordering
        atomicMin(&g_min_bits, __float_as_uint(bmin));
        atomicMax(&g_max_bits, __float_as_uint(bmax));
        __threadfence();
        atomicAdd(&g_arrive, 1u);
        // single-wave grid barrier (384 blocks <= 148*3 resident slots)
        while (atomicAdd(&g_arrive, 0u) < gridDim.x) __nanosleep(32);
        s_lo = __uint_as_float(atomicAdd(&g_min_bits, 0u));
        s_hi = __uint_as_float(atomicAdd(&g_max_bits, 0u));
    }
    __syncthreads();

    const float lo = s_lo;
    const float s  = PI_F / (s_hi - lo);

    // consecutive tid -> consecutive float4 of out [E,16]
    ((float4*)out)[(long)e * 4 + j] =
        make_float4((h.x - lo) * s, (h.y - lo) * s,
                    (h.z - lo) * s, (h.w - lo) * s);
}

extern "C" void kernel_launch(void* const* d_in, const int* in_sizes, int n_in,
                              void* d_out, int out_size) {
    const float* X    = (const float*)d_in[0];   // [8192, 64]
    const float* Ri   = (const float*)d_in[1];   // [8192, 24576]
    const float* Ro   = (const float*)d_in[2];   // [8192, 24576]
    const float* W_in = (const float*)d_in[3];   // [128, 16]
    const float* b_in = (const float*)d_in[4];   // [16]
    float* out = (float*)d_out;                  // [24576, 16]

    scan_kernel<<<SCAN_BLOCKS, SCAN_THREADS>>>((const uint4*)Ro, (const uint4*)Ri,
                                               X, W_in);

    // PDL launch: edge_kernel may begin scheduling before scan_kernel fully
    // completes; cudaGridDependencySynchronize() inside gates the data reads.
    cudaLaunchConfig_t cfg = {};
    cfg.gridDim  = dim3(EDGE_BLOCKS, 1, 1);
    cfg.blockDim = dim3(256, 1, 1);
    cfg.dynamicSmemBytes = 0;
    cfg.stream = 0;
    cudaLaunchAttribute attrs[1];
    attrs[0].id = cudaLaunchAttributeProgrammaticStreamSerialization;
    attrs[0].val.programmaticStreamSerializationAllowed = 1;
    cfg.attrs = attrs;
    cfg.numAttrs = 1;
    cudaLaunchKernelEx(&cfg, edge_kernel, b_in, out);
}

// round 17
// speedup vs baseline: 1.0075x; 1.0075x over previous
#include <cuda_runtime.h>
#include <cstdint>

#define N_NODES 8192
#define N_EDGES 24576
#define D_FEAT  64
#define N_QUBITS 16
#define PI_F 3.14159265358979f

#define SCAN_BLOCKS (148 * 16)           // 2368: 2 waves -> natural load balance
#define SCAN_THREADS 256
#define NODE_BLOCKS (N_NODES / 8)        // blocks 0..1023 run node prologue

#define EDGE_BLOCKS (N_EDGES * 4 / 256)  // 384 (4 lanes per edge)

// Scratch (no device mallocs allowed)
__device__ int      g_idx_o[N_EDGES];
__device__ int      g_idx_i[N_EDGES];
__device__ float    g_H[N_NODES * 32];   // [n][0:16]=X[n]@W_top, [n][16:32]=X[n]@W_bot
__device__ unsigned g_min_bits;
__device__ unsigned g_max_bits;
__device__ unsigned g_arrive;

// ---------------------------------------------------------------------------
// Fused: (a) node precompute prologue on blocks < NODE_BLOCKS,
//        (b) streaming scan of both one-hot incidence matrices.
// Streaming loads use __ldcs (evict-first) — data is single-use. All hot-loop
// indexing is 32-bit (total4 < 2^31). Nonzero (==1.0f) at linear pos p of
// [N_NODES, N_EDGES] row-major means idx[p % E] = p / E.
// ---------------------------------------------------------------------------
__global__ void __launch_bounds__(SCAN_THREADS)
scan_kernel(const uint4* __restrict__ Mo,
            const uint4* __restrict__ Mi,
            const float* __restrict__ X,
            const float* __restrict__ W) {
    const int tid = threadIdx.x;

    if (blockIdx.x == 0 && tid == 0) {
        g_min_bits = 0x7F800000u;   // +inf
        g_max_bits = 0x00000000u;   // relu outputs >= 0
        g_arrive   = 0u;
    }

    // ---- node prologue: Hs[n][q], Ht[n][q] for 8 nodes per block ----
    if (blockIdx.x < NODE_BLOCKS) {
        __shared__ float sW[2 * D_FEAT * N_QUBITS];   // 8 KB
        __shared__ float sX[8][D_FEAT];

        const int wid  = tid >> 5;
        const int lane = tid & 31;

        const float4* W4 = (const float4*)W;
        ((float4*)sW)[tid]       = W4[tid];
        ((float4*)sW)[tid + 256] = W4[tid + 256];

        const int n = blockIdx.x * 8 + wid;
        ((float2*)sX[wid])[lane] = ((const float2*)(X + (long)n * D_FEAT))[lane];
        __syncthreads();

        const int q    = lane & 15;
        const int half = lane >> 4;   // 0 = W[0:64], 1 = W[64:128]
        const float* w = sW + half * D_FEAT * N_QUBITS + q;
        const float* x = sX[wid];

        float acc = 0.0f;
#pragma unroll
        for (int d = 0; d < D_FEAT; d++)
            acc = fmaf(x[d], w[d * N_QUBITS], acc);

        g_H[(long)n * 32 + lane] = acc;   // coalesced 128B per warp
    }

    // ---- streaming scan (32-bit indices; evict-first loads) ----
    const unsigned total4 = (unsigned)(N_NODES / 4) * N_EDGES;  // 50,331,648
    const unsigned stride = SCAN_BLOCKS * SCAN_THREADS;
    unsigned i = blockIdx.x * SCAN_THREADS + tid;

#define PROCESS(v, I, IDX)                                              \
    if (((v).x | (v).y | (v).z | (v).w) != 0u) {                        \
        unsigned base = (I) * 4u;                                       \
        unsigned n = base / N_EDGES;                                    \
        unsigned e = base % N_EDGES;                                    \
        if ((v).x != 0u) IDX[e + 0] = n;                                \
        if ((v).y != 0u) IDX[e + 1] = n;                                \
        if ((v).z != 0u) IDX[e + 2] = n;                                \
        if ((v).w != 0u) IDX[e + 3] = n;                                \
    }

    for (; i + stride < total4; i += 2 * stride) {
        uint4 a0 = __ldcs(&Mo[i]);
        uint4 a1 = __ldcs(&Mo[i + stride]);
        uint4 b0 = __ldcs(&Mi[i]);
        uint4 b1 = __ldcs(&Mi[i + stride]);
        PROCESS(a0, i,          g_idx_o)
        PROCESS(a1, i + stride, g_idx_o)
        PROCESS(b0, i,          g_idx_i)
        PROCESS(b1, i + stride, g_idx_i)
    }
    for (; i < total4; i += stride) {
        uint4 a = __ldcs(&Mo[i]);
        uint4 b = __ldcs(&Mi[i]);
        PROCESS(a, i, g_idx_o)
        PROCESS(b, i, g_idx_i)
    }
#undef PROCESS
    // implicit programmatic-launch completion at kernel end: all stores above
    // are visible to the PDL-gated consumer after cudaGridDependencySynchronize.
}

// ---------------------------------------------------------------------------
// Edge stage, 4 lanes per edge: lane j of edge e computes qubits [4j, 4j+4)
//   h = relu(Hs[src[e]][4j..] + Ht[tgt[e]][4j..] + b[4j..])
// Launched with PDL: blocks start while scan_kernel drains; scan-independent
// setup (bias load, index math) runs before cudaGridDependencySynchronize().
// Global min/max via atomics + single-wave grid barrier (384 blocks <= 444
// resident slots), normalize in-register, coalesced store.
// ---------------------------------------------------------------------------
__global__ void __launch_bounds__(256, 3)
edge_kernel(const float* __restrict__ b,
            float* __restrict__ out) {
    __shared__ float s_min[8], s_max[8];
    __shared__ float s_lo, s_hi;

    const int tid = threadIdx.x;
    const int j   = tid & 3;
    const int e   = blockIdx.x * 64 + (tid >> 2);

    // scan-independent work first (overlaps with scan tail under PDL)
    const float4 bb = ((const float4*)b)[j];

    // wait for scan_kernel's writes (g_idx_*, g_H, min/max reset) to be visible
    cudaGridDependencySynchronize();

    const int src = g_idx_o[e];
    const int tgt = g_idx_i[e];

    const float4 a = ((const float4*)(g_H + (long)src * 32))[j];
    const float4 c = ((const float4*)(g_H + (long)tgt * 32 + 16))[j];

    float4 h;
    h.x = fmaxf(a.x + c.x + bb.x, 0.0f);
    h.y = fmaxf(a.y + c.y + bb.y, 0.0f);
    h.z = fmaxf(a.z + c.z + bb.z, 0.0f);
    h.w = fmaxf(a.w + c.w + bb.w, 0.0f);

    float tmin = fminf(fminf(h.x, h.y), fminf(h.z, h.w));
    float tmax = fmaxf(fmaxf(h.x, h.y), fmaxf(h.z, h.w));
#pragma unroll
    for (int off = 16; off > 0; off >>= 1) {
        tmin = fminf(tmin, __shfl_xor_sync(0xFFFFFFFF, tmin, off));
        tmax = fmaxf(tmax, __shfl_xor_sync(0xFFFFFFFF, tmax, off));
    }
    const int wid = tid >> 5, lid = tid & 31;
    if (lid == 0) { s_min[wid] = tmin; s_max[wid] = tmax; }
    __syncthreads();

    if (tid == 0) {
        float bmin = s_min[0], bmax = s_max[0];
#pragma unroll
        for (int w = 1; w < 8; w++) {
            bmin = fminf(bmin, s_min[w]);
            bmax = fmaxf(bmax, s_max[w]);
        }
        // nonneg floats: uint bit pattern preserves ordering
        atomicMin(&g_min_bits, __float_as_uint(bmin));
        atomicMax(&g_max_bits, __float_as_uint(bmax));
        __threadfence();
        atomicAdd(&g_arrive, 1u);
        // single-wave grid barrier (384 blocks <= 148*3 resident slots)
        while (atomicAdd(&g_arrive, 0u) < gridDim.x) __nanosleep(32);
        s_lo = __uint_as_float(atomicAdd(&g_min_bits, 0u));
        s_hi = __uint_as_float(atomicAdd(&g_max_bits, 0u));
    }
    __syncthreads();

    const float lo = s_lo;
    const float s  = PI_F / (s_hi - lo);

    // consecutive tid -> consecutive float4 of out [E,16]
    ((float4*)out)[(long)e * 4 + j] =
        make_float4((h.x - lo) * s, (h.y - lo) * s,
                    (h.z - lo) * s, (h.w - lo) * s);
}

extern "C" void kernel_launch(void* const* d_in, const int* in_sizes, int n_in,
                              void* d_out, int out_size) {
    const float* X    = (const float*)d_in[0];   // [8192, 64]
    const float* Ri   = (const float*)d_in[1];   // [8192, 24576]
    const float* Ro   = (const float*)d_in[2];   // [8192, 24576]
    const float* W_in = (const float*)d_in[3];   // [128, 16]
    const float* b_in = (const float*)d_in[4];   // [16]
    float* out = (float*)d_out;                  // [24576, 16]

    scan_kernel<<<SCAN_BLOCKS, SCAN_THREADS>>>((const uint4*)Ro, (const uint4*)Ri,
                                               X, W_in);

    // PDL launch: edge_kernel may begin scheduling before scan_kernel fully
    // completes; cudaGridDependencySynchronize() inside gates the data reads.
    cudaLaunchConfig_t cfg = {};
    cfg.gridDim  = dim3(EDGE_BLOCKS, 1, 1);
    cfg.blockDim = dim3(256, 1, 1);
    cfg.dynamicSmemBytes = 0;
    cfg.stream = 0;
    cudaLaunchAttribute attrs[1];
    attrs[0].id = cudaLaunchAttributeProgrammaticStreamSerialization;
    attrs[0].val.programmaticStreamSerializationAllowed = 1;
    cfg.attrs = attrs;
    cfg.numAttrs = 1;
    cudaLaunchKernelEx(&cfg, edge_kernel, b_in, out);
}